// round 1
// baseline (speedup 1.0000x reference)
#include <cuda_runtime.h>

// GARCH(1,1): s[0] = var(r, ddof=1); s[t] = omega + alpha*r[t-1]^2 + beta*s[t-1]
// T = 2^24. Parallelized via exponentially-windowed seeds (beta^128 ~ 4e-13).

#define T_TOTAL   16777216
#define WWIN      128            // seed window length
#define CPT       32             // outputs per thread
#define NTHREADS  256
#define TILE      (NTHREADS * CPT)     // 8192 outputs per block
#define SH_RAW    (TILE + WWIN)        // 8320 r^2 values per block
#define SWZ(i)    ((i) + ((i) >> 5))   // pad every 32 floats -> conflict-free stride-32
#define SH_SIZE   (SH_RAW + (SH_RAW >> 5) + 4)   // 8584 floats

#define VAR_BLOCKS  1024
#define VAR_THREADS 256

__device__ float2 g_partials[VAR_BLOCKS];
__device__ float  g_s0;

// ---------------------------------------------------------------------------
// Pass 1: per-block partial (sum, sumsq) over returns, float4 loads.
// ---------------------------------------------------------------------------
__global__ void __launch_bounds__(VAR_THREADS)
var_reduce_kernel(const float4* __restrict__ r4) {
    const int tid    = blockIdx.x * VAR_THREADS + threadIdx.x;
    const int stride = VAR_BLOCKS * VAR_THREADS;
    float s = 0.f, ss = 0.f;
    for (int i = tid; i < T_TOTAL / 4; i += stride) {
        float4 v = r4[i];
        s  += (v.x + v.y) + (v.z + v.w);
        ss  = fmaf(v.x, v.x, ss);
        ss  = fmaf(v.y, v.y, ss);
        ss  = fmaf(v.z, v.z, ss);
        ss  = fmaf(v.w, v.w, ss);
    }
    #pragma unroll
    for (int o = 16; o > 0; o >>= 1) {
        s  += __shfl_down_sync(0xffffffffu, s,  o);
        ss += __shfl_down_sync(0xffffffffu, ss, o);
    }
    __shared__ float ws[8], wss[8];
    const int lane = threadIdx.x & 31, wid = threadIdx.x >> 5;
    if (lane == 0) { ws[wid] = s; wss[wid] = ss; }
    __syncthreads();
    if (threadIdx.x == 0) {
        float a = 0.f, b = 0.f;
        #pragma unroll
        for (int i = 0; i < VAR_THREADS / 32; i++) { a += ws[i]; b += wss[i]; }
        g_partials[blockIdx.x] = make_float2(a, b);
    }
}

// ---------------------------------------------------------------------------
// Pass 2: final double-precision reduction -> s0 = var(r, ddof=1)
// ---------------------------------------------------------------------------
__global__ void __launch_bounds__(256)
var_finalize_kernel() {
    double s = 0.0, ss = 0.0;
    for (int i = threadIdx.x; i < VAR_BLOCKS; i += 256) {
        float2 p = g_partials[i];
        s += (double)p.x; ss += (double)p.y;
    }
    #pragma unroll
    for (int o = 16; o > 0; o >>= 1) {
        s  += __shfl_down_sync(0xffffffffu, s,  o);
        ss += __shfl_down_sync(0xffffffffu, ss, o);
    }
    __shared__ double ds[8], dss[8];
    const int lane = threadIdx.x & 31, wid = threadIdx.x >> 5;
    if (lane == 0) { ds[wid] = s; dss[wid] = ss; }
    __syncthreads();
    if (threadIdx.x == 0) {
        double a = 0.0, b = 0.0;
        #pragma unroll
        for (int i = 0; i < 8; i++) { a += ds[i]; b += dss[i]; }
        double var = (b - a * a / (double)T_TOTAL) / (double)(T_TOTAL - 1);
        g_s0 = (float)var;
    }
}

// ---------------------------------------------------------------------------
// Pass 3: main GARCH kernel. Each block: tile of 8192 outputs.
//   - load r^2 tile (+W halo) into swizzled shared
//   - per-thread windowed Horner seed (W=128)
//   - exact recurrence for 32 consecutive outputs (registers)
//   - transpose through shared -> coalesced stores
// ---------------------------------------------------------------------------
__global__ void __launch_bounds__(NTHREADS)
garch_main_kernel(const float* __restrict__ r,
                  const float* __restrict__ p_omega,
                  const float* __restrict__ p_alpha,
                  const float* __restrict__ p_beta,
                  float* __restrict__ out) {
    __shared__ float sh[SH_SIZE];

    const float omega = __ldg(p_omega);
    const float alpha = __ldg(p_alpha);
    const float beta  = __ldg(p_beta);
    const float g_inf = omega / (1.0f - beta);

    const int T0 = blockIdx.x * TILE;

    // Load r^2 tile into swizzled shared memory. Global indices [T0-W, T0-W+SH_RAW).
    for (int i = threadIdx.x; i < SH_RAW; i += NTHREADS) {
        const int gidx = T0 - WWIN + i;
        float v = 0.0f;
        if (gidx >= 0 && gidx < T_TOTAL) v = r[gidx];
        sh[SWZ(i)] = v * v;
    }
    __syncthreads();

    const int k  = threadIdx.x;
    const int t0 = T0 + k * CPT;

    float seed;
    if (blockIdx.x == 0) {
        // Exact seed near the start: s[t0] = beta^K*s0 + g*(1-beta^K) + alpha*Horner
        const int K = (t0 < WWIN) ? t0 : WWIN;
        const float bk = __powf(beta, (float)K);
        float acc = 0.0f;
        // r indices t0-K .. t0-1 ; shared raw index = rI + W  (T0 == 0)
        for (int i = t0 - K; i < t0; i++)
            acc = fmaf(acc, beta, sh[SWZ(i + WWIN)]);
        seed = fmaf(bk, g_s0, g_inf * (1.0f - bk)) + alpha * acc;
    } else {
        // Generic windowed seed: truncation error ~ beta^128 ~ 4e-13
        float acc = 0.0f;
        const int base = k * CPT;   // raw shared index of r[t0 - W]
        #pragma unroll
        for (int j = 0; j < WWIN; j++)
            acc = fmaf(acc, beta, sh[SWZ(base + j)]);
        const float bk = __powf(beta, (float)WWIN);
        seed = fmaf(g_inf, (1.0f - bk), alpha * acc);
    }

    // Exact recurrence over this thread's CPT consecutive outputs.
    float o[CPT];
    float s = seed;
    #pragma unroll
    for (int idx = 0; idx < CPT; idx++) {
        o[idx] = s;
        const float r2 = sh[SWZ(k * CPT + idx + WWIN)];  // r[t0+idx]^2
        s = fmaf(beta, s, fmaf(alpha, r2, omega));
    }
    __syncthreads();   // done reading r^2; reuse shared as transpose buffer

    // Stage: out for t = T0 + k*CPT + idx lives at sh[idx*257 + k]  (conflict-free)
    #pragma unroll
    for (int idx = 0; idx < CPT; idx++)
        sh[idx * 257 + k] = o[idx];
    __syncthreads();

    // Coalesced stores: tile position p -> thread p>>5, local idx p&31
    for (int p = threadIdx.x; p < TILE; p += NTHREADS)
        out[T0 + p] = sh[(p & 31) * 257 + (p >> 5)];
}

// ---------------------------------------------------------------------------
extern "C" void kernel_launch(void* const* d_in, const int* in_sizes, int n_in,
                              void* d_out, int out_size) {
    const float* r       = (const float*)d_in[0];
    const float* p_omega = (const float*)d_in[1];
    const float* p_alpha = (const float*)d_in[2];
    const float* p_beta  = (const float*)d_in[3];
    float* out = (float*)d_out;

    var_reduce_kernel<<<VAR_BLOCKS, VAR_THREADS>>>((const float4*)r);
    var_finalize_kernel<<<1, 256>>>();
    garch_main_kernel<<<T_TOTAL / TILE, NTHREADS>>>(r, p_omega, p_alpha, p_beta, out);
}

// round 2
// speedup vs baseline: 1.1251x; 1.1251x over previous
#include <cuda_runtime.h>

// GARCH(1,1): s[0] = var(r, ddof=1); s[t] = omega + alpha*r[t-1]^2 + beta*s[t-1]
// T = 2^24. Single fused pass:
//   - windowed seeds (beta^128 ~ 4e-13) via shared per-chunk Horner factors
//   - variance via deterministic fixed-point int64 atomics
//   - last block serially fixes out[0..127] exactly.

#define T_TOTAL   16777216
#define WWIN      128
#define CPT       32
#define NTHREADS  256
#define TILE      (NTHREADS * CPT)        // 8192 outputs / block
#define NBLOCKS   (T_TOTAL / TILE)        // 2048
#define SH_RAW    (TILE + WWIN)           // 8320 r^2 values
#define SWZ(i)    ((i) + ((i) >> 5))      // stride-32 -> stride-33, conflict-free
#define SH_SIZE   8584                    // >= max(SWZ(8319)+1, 32*257)

#define SCALE_S   4398046511104.0         // 2^42  (sum r)
#define SCALE_SS  70368744177664.0        // 2^46  (sum r^2)

__device__ unsigned long long g_sum_fx;
__device__ unsigned long long g_ss_fx;
__device__ unsigned int       g_done;

__global__ void init_kernel() {
    g_sum_fx = 0ULL; g_ss_fx = 0ULL; g_done = 0u;
}

__global__ void __launch_bounds__(NTHREADS)
garch_fused_kernel(const float* __restrict__ r,
                   const float* __restrict__ p_omega,
                   const float* __restrict__ p_alpha,
                   const float* __restrict__ p_beta,
                   float* __restrict__ out) {
    __shared__ float sh[SH_SIZE];            // r^2 tile, later reused as transpose buffer
    __shared__ float shH[NTHREADS + 4];      // per-chunk Horner factors
    __shared__ float red[16];                // warp partials: [0:8)=sum, [8:16)=sumsq

    const float omega = __ldg(p_omega);
    const float alpha = __ldg(p_alpha);
    const float beta  = __ldg(p_beta);
    const float g_inf = omega / (1.0f - beta);
    // beta^32 by repeated squaring
    const float b2  = beta * beta;
    const float b4  = b2 * b2;
    const float b8  = b4 * b4;
    const float b16 = b8 * b8;
    const float b32 = b16 * b16;
    const float b64  = b32 * b32;
    const float b128 = b64 * b64;            // ~4e-13

    const int T0 = blockIdx.x * TILE;
    const int k  = threadIdx.x;

    // ---- Fill shared with r^2 (float4 loads) + accumulate var partials (own tile only)
    float vs = 0.f, vss = 0.f;
    {
        const float4* r4 = (const float4*)r;
        const int g4base = (T0 - WWIN) >> 2;             // divisible: T0,WWIN mult of 4
        for (int i4 = k; i4 < SH_RAW / 4; i4 += NTHREADS) {
            const int g4 = g4base + i4;
            float4 v = make_float4(0.f, 0.f, 0.f, 0.f);
            if (g4 >= 0) v = r4[g4];                     // upper bound always in range
            const int i = i4 * 4;
            if (i >= WWIN) {                             // own-tile elements only
                vs += (v.x + v.y) + (v.z + v.w);
                vss = fmaf(v.x, v.x, vss);
                vss = fmaf(v.y, v.y, vss);
                vss = fmaf(v.z, v.z, vss);
                vss = fmaf(v.w, v.w, vss);
            }
            sh[SWZ(i + 0)] = v.x * v.x;
            sh[SWZ(i + 1)] = v.y * v.y;
            sh[SWZ(i + 2)] = v.z * v.z;
            sh[SWZ(i + 3)] = v.w * v.w;
        }
    }
    // warp-reduce var partials
    #pragma unroll
    for (int o = 16; o > 0; o >>= 1) {
        vs  += __shfl_down_sync(0xffffffffu, vs,  o);
        vss += __shfl_down_sync(0xffffffffu, vss, o);
    }
    const int lane = k & 31, wid = k >> 5;
    if (lane == 0) { red[wid] = vs; red[8 + wid] = vss; }
    __syncthreads();

    if (k == 0) {
        float bs = 0.f, bss = 0.f;
        #pragma unroll
        for (int i = 0; i < 8; i++) { bs += red[i]; bss += red[8 + i]; }
        atomicAdd(&g_sum_fx, (unsigned long long)(long long)llrint((double)bs  * SCALE_S));
        atomicAdd(&g_ss_fx,  (unsigned long long)(long long)llrint((double)bss * SCALE_SS));
    }

    // ---- Per-chunk Horner: H_c = sum_j beta^(31-j) * r2[c*32+j]
    // Thread k owns output chunk (k+4); threads 0..3 also cover the 4 halo chunks.
    float rq[CPT];
    {
        const int base = (k + 4) * 32;
        #pragma unroll
        for (int j = 0; j < CPT; j++) rq[j] = sh[SWZ(base + j)];
    }
    float H = 0.f;
    #pragma unroll
    for (int j = 0; j < CPT; j++) H = fmaf(H, beta, rq[j]);
    shH[k + 4] = H;
    if (k < 4) {
        const int hb = k * 32;
        float Hh = 0.f;
        #pragma unroll
        for (int j = 0; j < 32; j++) Hh = fmaf(Hh, beta, sh[SWZ(hb + j)]);
        shH[k] = Hh;
    }
    __syncthreads();   // H's ready; everyone done reading r^2 region -> reusable

    // ---- Seed: s[t0] ~= g_inf*(1-b128) + alpha*(H_k*b96 + H_{k+1}*b64 + H_{k+2}*b32 + H_{k+3})
    float acc = shH[k];
    acc = fmaf(acc, b32, shH[k + 1]);
    acc = fmaf(acc, b32, shH[k + 2]);
    acc = fmaf(acc, b32, shH[k + 3]);
    float s = fmaf(alpha, acc, g_inf * (1.0f - b128));

    // ---- Exact recurrence over CPT consecutive outputs, streamed into transpose buffer
    #pragma unroll
    for (int idx = 0; idx < CPT; idx++) {
        sh[idx * 257 + k] = s;                           // conflict-free (stride 1)
        s = fmaf(beta, s, fmaf(alpha, rq[idx], omega));
    }
    __syncthreads();

    // ---- Coalesced float4 stores: p = 4q, addr = (p&31)*257 + (p>>5)
    {
        float4* out4 = (float4*)(out + T0);
        for (int q = k; q < TILE / 4; q += NTHREADS) {
            const int hi  = q >> 3;
            const int lo4 = (q & 7) * 4;
            float4 v;
            v.x = sh[(lo4 + 0) * 257 + hi];
            v.y = sh[(lo4 + 1) * 257 + hi];
            v.z = sh[(lo4 + 2) * 257 + hi];
            v.w = sh[(lo4 + 3) * 257 + hi];
            out4[q] = v;
        }
    }

    // ---- Last block: exact serial fix for out[0..127] using true s0
    __threadfence();
    __syncthreads();
    if (k == 0) {
        const unsigned int old = atomicAdd(&g_done, 1u);
        if (old == NBLOCKS - 1) {
            const double sum = (double)(long long)atomicAdd(&g_sum_fx, 0ULL) / SCALE_S;
            const double ssq = (double)(long long)atomicAdd(&g_ss_fx,  0ULL) / SCALE_SS;
            const double var = (ssq - sum * sum / (double)T_TOTAL) / (double)(T_TOTAL - 1);
            float sv = (float)var;
            out[0] = sv;
            for (int t = 1; t < WWIN; t++) {
                const float rv = r[t - 1];
                sv = fmaf(beta, sv, fmaf(alpha, rv * rv, omega));
                out[t] = sv;
            }
        }
    }
}

// ---------------------------------------------------------------------------
extern "C" void kernel_launch(void* const* d_in, const int* in_sizes, int n_in,
                              void* d_out, int out_size) {
    const float* r       = (const float*)d_in[0];
    const float* p_omega = (const float*)d_in[1];
    const float* p_alpha = (const float*)d_in[2];
    const float* p_beta  = (const float*)d_in[3];
    float* out = (float*)d_out;

    init_kernel<<<1, 1>>>();
    garch_fused_kernel<<<NBLOCKS, NTHREADS>>>(r, p_omega, p_alpha, p_beta, out);
}